// round 10
// baseline (speedup 1.0000x reference)
#include <cuda_runtime.h>
#include <cuda_fp16.h>
#include <stdint.h>

#define Bb        32
#define NPAIR     674
#define DPAIR     1636
#define DPAIR_PAD 1640   // fp16 row stride: 1640*2 = 3280 B, 16B-aligned for cp.async
#define DIN       768
#define DHID      512
#define DOUT      256
#define MROWS     21568  // Bb * NPAIR

// ---- scratch (static device globals) ----
__device__ __half g_cpeh[(size_t)MROWS * DPAIR_PAD];   // fp16 cpe, padded stride
__device__ __half g_Wih[DPAIR * DIN];                  // fp16 Wi
__device__ __half g_W18h[DIN * DHID];                  // fp16 W1[8]
__device__ __half g_Wch[DPAIR * DHID];                 // fp16 Wi @ W1[8]
__device__ __half g_Wdh[DHID * DOUT];                  // fp16 W2[8] @ Wo1
__device__ __half g_hph[(size_t)MROWS * DHID];         // fp16 h_p
__device__ float  g_bc[DHID];
__device__ float  g_g2[Bb * DHID];
__device__ float  g_bd[DOUT];

__device__ __forceinline__ void cp16(uint32_t saddr, const void* gptr, bool valid) {
    int sz = valid ? 16 : 0;   // src-size 0 -> zero-fill, no global read
    asm volatile("cp.async.cg.shared.global [%0], [%1], 16, %2;"
                 :: "r"(saddr), "l"(gptr), "r"(sz));
}
__device__ __forceinline__ void cp_commit() { asm volatile("cp.async.commit_group;"); }
__device__ __forceinline__ void cp_wait1()  { asm volatile("cp.async.wait_group 1;"); }

__device__ __forceinline__ void ldsm_x4(uint32_t* r, uint32_t addr) {
    asm volatile("ldmatrix.sync.aligned.m8n8.x4.shared.b16 {%0,%1,%2,%3}, [%4];"
                 : "=r"(r[0]), "=r"(r[1]), "=r"(r[2]), "=r"(r[3]) : "r"(addr));
}
__device__ __forceinline__ void ldsm_x4_t(uint32_t* r, uint32_t addr) {
    asm volatile("ldmatrix.sync.aligned.m8n8.x4.trans.shared.b16 {%0,%1,%2,%3}, [%4];"
                 : "=r"(r[0]), "=r"(r[1]), "=r"(r[2]), "=r"(r[3]) : "r"(addr));
}
__device__ __forceinline__ void mma_f16(float* d, const uint32_t* a, const uint32_t* b) {
    asm volatile(
        "mma.sync.aligned.m16n8k16.row.col.f32.f16.f16.f32 "
        "{%0,%1,%2,%3}, {%4,%5,%6,%7}, {%8,%9}, {%0,%1,%2,%3};"
        : "+f"(d[0]), "+f"(d[1]), "+f"(d[2]), "+f"(d[3])
        : "r"(a[0]), "r"(a[1]), "r"(a[2]), "r"(a[3]), "r"(b[0]), "r"(b[1]));
}

// ============================================================================
// Pipelined FP16 MMA GEMM (fp32 accumulate). Block tile (NWM*64) x BN, BK=32,
// 3-stage cp.async, ldmatrix fragment loads. Warp tile 64 x WTN (m16n8k16),
// WTN = BN / (NTHREADS/32/NWM).
// A row-major [M,K] fp16 with row stride lda (lda*2 must be 16B-aligned),
// B row-major [K,N] fp16 (N % BN == 0).
// smem A[stage][BM][40], B[stage][32][BN+8] (strides multiple of 16B, bank-
// conflict-free ldmatrix as verified at BN=128/256).
// OOB: A rows m>=M zero-filled; B k-rows >= K zero-filled (pad garbage * 0).
// EPI=0: C = half(A@B)
// EPI=1: C = half(relu((A@B + g_bc[n] + g_g2[row/674][n]) * 0.5))
// EPI=2: out[row] = dot(relu(A@B + g_bd), Wo2) + bo2   (C unused)
// ============================================================================
template<int NWM, int BN, int NTHREADS, int EPI>
__global__ __launch_bounds__(NTHREADS) void hgemm(
    const __half* __restrict__ A, int lda, const __half* __restrict__ Bm,
    __half* __restrict__ C, int M, int N, int K,
    const float* __restrict__ Wo2, const float* __restrict__ bo2,
    float* __restrict__ out)
{
    constexpr int BM   = NWM * 64;
    constexpr int NWN  = NTHREADS / 32 / NWM;
    constexpr int WTN  = BN / NWN;     // warp tile n (32 or 64)
    constexpr int NTN  = WTN / 8;      // n8 sub-tiles per warp
    constexpr int NPB  = WTN / 16;     // B ldmatrix.x4 per k16
    constexpr int SA   = 40;           // halves per A smem row (80 B)
    constexpr int SB   = BN + 8;       // halves per B smem row
    constexpr int ASTG = BM * SA;
    constexpr int BSTG = 32 * SB;

    extern __shared__ char smraw[];
    const uint32_t smb  = (uint32_t)__cvta_generic_to_shared(smraw);
    const uint32_t bsmb = smb + 3 * ASTG * 2;

    const int tid  = threadIdx.x;
    const int lane = tid & 31;
    const int wid  = tid >> 5;
    const int wm   = wid / NWN;
    const int wn   = wid % NWN;
    const int m0   = blockIdx.y * BM;
    const int n0   = blockIdx.x * BN;
    const int q    = lane & 3;
    const int g    = lane >> 2;

    float acc[4][NTN][4];
    #pragma unroll
    for (int mt = 0; mt < 4; mt++)
        #pragma unroll
        for (int nt = 0; nt < NTN; nt++)
            #pragma unroll
            for (int i = 0; i < 4; i++) acc[mt][nt][i] = 0.f;

    const int niter = (K + 31) >> 5;

    auto load_stage = [&](int s, int k0) {
        const uint32_t abase = smb + (uint32_t)(s * ASTG) * 2;
        for (int qx = tid; qx < BM * 4; qx += NTHREADS) {
            const int row  = qx >> 2;
            const int kseg = (qx & 3) * 8;
            const bool v = (m0 + row < M) && (k0 + kseg < K);
            cp16(abase + (uint32_t)(row * SA + kseg) * 2,
                 A + (size_t)(m0 + row) * lda + k0 + kseg, v);
        }
        const uint32_t bbase = bsmb + (uint32_t)(s * BSTG) * 2;
        for (int qx = tid; qx < 32 * (BN / 8); qx += NTHREADS) {
            const int row  = qx / (BN / 8);
            const int nseg = (qx % (BN / 8)) * 8;
            const bool v = (k0 + row) < K;
            cp16(bbase + (uint32_t)(row * SB + nseg) * 2,
                 Bm + (size_t)(k0 + row) * N + n0 + nseg, v);
        }
    };

    load_stage(0, 0);
    cp_commit();
    load_stage(1, 32);
    cp_commit();

    const uint32_t a_ld0 = smb +
        (uint32_t)((wm * 64 + (lane & 15)) * SA + (lane >> 4) * 8) * 2;
    const uint32_t b_ld0 = bsmb +
        (uint32_t)(((lane & 7) + ((lane >> 3) & 1) * 8) * SB
                   + wn * WTN + (lane >> 4) * 8) * 2;

    for (int it = 0; it < niter; it++) {
        cp_wait1();
        __syncthreads();

        const int nxt = it + 2;
        if (nxt < niter) load_stage(nxt % 3, nxt * 32);
        cp_commit();

        const uint32_t ast = (uint32_t)((it % 3) * ASTG) * 2;
        const uint32_t bst = (uint32_t)((it % 3) * BSTG) * 2;

        #pragma unroll
        for (int k16 = 0; k16 < 2; k16++) {
            uint32_t af[4][4], bf[NPB][4];
            const uint32_t aaddr = a_ld0 + ast + (uint32_t)(k16 * 16) * 2;
            #pragma unroll
            for (int mt = 0; mt < 4; mt++)
                ldsm_x4(af[mt], aaddr + (uint32_t)(mt * 16 * SA) * 2);
            const uint32_t baddr = b_ld0 + bst + (uint32_t)(k16 * 16 * SB) * 2;
            #pragma unroll
            for (int np = 0; np < NPB; np++)
                ldsm_x4_t(bf[np], baddr + (uint32_t)(np * 16) * 2);
            #pragma unroll
            for (int mt = 0; mt < 4; mt++)
                #pragma unroll
                for (int nt = 0; nt < NTN; nt++)
                    mma_f16(acc[mt][nt], af[mt], &bf[nt >> 1][(nt & 1) * 2]);
        }
        __syncthreads();
    }

    if (EPI == 0 || EPI == 1) {
        #pragma unroll
        for (int mt = 0; mt < 4; mt++) {
            #pragma unroll
            for (int half = 0; half < 2; half++) {
                const int r = m0 + wm * 64 + mt * 16 + g + half * 8;
                if (r >= M) continue;
                const float* g2r = (EPI == 1) ? (g_g2 + (r / NPAIR) * DHID) : nullptr;
                #pragma unroll
                for (int nt = 0; nt < NTN; nt++) {
                    const int c = n0 + wn * WTN + nt * 8 + 2 * q;
                    float v0 = acc[mt][nt][half * 2 + 0];
                    float v1 = acc[mt][nt][half * 2 + 1];
                    if (EPI == 1) {
                        v0 = fmaxf((v0 + g_bc[c    ] + g2r[c    ]) * 0.5f, 0.f);
                        v1 = fmaxf((v1 + g_bc[c + 1] + g2r[c + 1]) * 0.5f, 0.f);
                    }
                    *(__half2*)(C + (size_t)r * N + c) = __floats2half2_rn(v0, v1);
                }
            }
        }
    } else {
        // EPI == 2: fused out[r] = dot(relu(acc + g_bd), Wo2) + bo2
        float bdv[NTN][2], wv[NTN][2];
        #pragma unroll
        for (int nt = 0; nt < NTN; nt++)
            #pragma unroll
            for (int j = 0; j < 2; j++) {
                const int c = wn * WTN + nt * 8 + 2 * q + j;
                bdv[nt][j] = g_bd[c];
                wv[nt][j]  = Wo2[c];
            }
        float* red = (float*)smraw;   // [BM][NWN]; all cp groups drained
        #pragma unroll
        for (int mt = 0; mt < 4; mt++) {
            #pragma unroll
            for (int half = 0; half < 2; half++) {
                float p = 0.f;
                #pragma unroll
                for (int nt = 0; nt < NTN; nt++)
                    #pragma unroll
                    for (int j = 0; j < 2; j++) {
                        const float h = fmaxf(acc[mt][nt][half * 2 + j] + bdv[nt][j], 0.f);
                        p = fmaf(h, wv[nt][j], p);
                    }
                p += __shfl_xor_sync(0xffffffffu, p, 1);
                p += __shfl_xor_sync(0xffffffffu, p, 2);
                if (q == 0) {
                    const int rl = wm * 64 + mt * 16 + g + half * 8;
                    red[rl * NWN + wn] = p;
                }
            }
        }
        __syncthreads();
        if (tid < BM) {
            float s = bo2[0];
            #pragma unroll
            for (int w = 0; w < NWN; w++) s += red[tid * NWN + w];
            if (m0 + tid < M) out[m0 + tid] = s;
        }
    }
}

// ---- fp32 -> fp16 bulk convert, contiguous (stride preserved) ----
__global__ void cvt_kernel(const float* __restrict__ in, __half* __restrict__ out, int n2)
{
    const float2* i2 = (const float2*)in;
    __half2* o2 = (__half2*)out;
    for (int i = blockIdx.x * blockDim.x + threadIdx.x; i < n2;
         i += gridDim.x * blockDim.x)
        o2[i] = __float22half2_rn(i2[i]);
}

// ---- cpe fp32 [MROWS x DPAIR] -> fp16 padded [MROWS x DPAIR_PAD], pad zeroed ----
__global__ void cvt_cpe_kernel(const float* __restrict__ in, __half* __restrict__ out)
{
    const int nseg = DPAIR / 4;   // 409 float4 segs per row
    for (int idx = blockIdx.x * blockDim.x + threadIdx.x; idx < MROWS * nseg;
         idx += gridDim.x * blockDim.x) {
        const int row = idx / nseg;
        const int c4  = (idx % nseg) * 4;
        float4 v = *(const float4*)(in + (size_t)row * DPAIR + c4);
        __half2* dst = (__half2*)(out + (size_t)row * DPAIR_PAD + c4);
        dst[0] = __floats2half2_rn(v.x, v.y);
        dst[1] = __floats2half2_rn(v.z, v.w);
        if (c4 == 0) {   // zero the 4 pad halves of this row
            __half2* pad = (__half2*)(out + (size_t)row * DPAIR_PAD + DPAIR);
            pad[0] = __half2half2(__float2half(0.f));
            pad[1] = __half2half2(__float2half(0.f));
        }
    }
}

// ---- small precompute kernels ----
__global__ void bc_kernel(const float* __restrict__ bi, const float* __restrict__ W18,
                          const float* __restrict__ b18)
{
    const int n = blockIdx.x * blockDim.x + threadIdx.x;
    float s = 0.f;
    for (int k = 0; k < DIN; k++) s = fmaf(bi[k], W18[(size_t)k * DHID + n], s);
    g_bc[n] = s + b18[n];
}

__global__ void g2_kernel(const float* __restrict__ ac, const float* __restrict__ W12,
                          const float* __restrict__ b12)
{
    const int b = blockIdx.x;
    const int n = threadIdx.x;
    const float scale = rsqrtf((float)NPAIR);
    float s = 0.f;
    const float* arow = ac + (size_t)b * DIN;
    for (int k = 0; k < DIN; k++) s = fmaf(arow[k], W12[(size_t)k * DHID + n], s);
    g_g2[b * DHID + n] = s * scale + b12[n];
}

// Wd = W2[8] @ Wo1 -> fp16. 16 m-rows per block via smem tile, Wo1 coalesced.
__global__ __launch_bounds__(256) void wd_kernel(const float* __restrict__ W28,
                                                 const float* __restrict__ Wo1)
{
    __shared__ float w28s[16][DOUT];
    const int m0 = blockIdx.x * 16;
    const int n  = threadIdx.x;
    for (int i = threadIdx.x; i < 16 * DOUT; i += 256)
        w28s[i >> 8][i & 255] = W28[(size_t)(m0 + (i >> 8)) * DOUT + (i & 255)];
    __syncthreads();
    float acc[16];
    #pragma unroll
    for (int mm = 0; mm < 16; mm++) acc[mm] = 0.f;
    for (int k = 0; k < DOUT; k++) {
        const float w = Wo1[(size_t)k * DOUT + n];
        #pragma unroll
        for (int mm = 0; mm < 16; mm++) acc[mm] = fmaf(w28s[mm][k], w, acc[mm]);
    }
    #pragma unroll
    for (int mm = 0; mm < 16; mm++)
        g_Wdh[(size_t)(m0 + mm) * DOUT + n] = __float2half_rn(acc[mm]);
}

__global__ void bd_kernel(const float* __restrict__ b28, const float* __restrict__ Wo1,
                          const float* __restrict__ bo1)
{
    const int n = threadIdx.x;
    float s = 0.f;
    for (int k = 0; k < DOUT; k++) s = fmaf(b28[k], Wo1[(size_t)k * DOUT + n], s);
    g_bd[n] = s + bo1[n];
}

// ============================================================================
// Launch. Live inputs: cpe(0), ac(3), Wi(4), bi(5), W1(6), b1(7), W2(8),
// b2(9), Wo1(10), bo1(11), Wo2(12), bo2(13). he/hc dead.
// ============================================================================
extern "C" void kernel_launch(void* const* d_in, const int* in_sizes, int n_in,
                              void* d_out, int out_size)
{
    const float* cpe = (const float*)d_in[0];
    const float* ac  = (const float*)d_in[3];
    const float* Wi  = (const float*)d_in[4];
    const float* bi  = (const float*)d_in[5];
    const float* W1  = (const float*)d_in[6];
    const float* b1  = (const float*)d_in[7];
    const float* W2  = (const float*)d_in[8];
    const float* b2  = (const float*)d_in[9];
    const float* Wo1 = (const float*)d_in[10];
    const float* bo1 = (const float*)d_in[11];
    const float* Wo2 = (const float*)d_in[12];
    const float* bo2 = (const float*)d_in[13];
    float* out = (float*)d_out;

    __half *pCpeh, *pWih, *pW18h, *pWch, *pWdh, *pHph;
    cudaGetSymbolAddress((void**)&pCpeh, g_cpeh);
    cudaGetSymbolAddress((void**)&pWih,  g_Wih);
    cudaGetSymbolAddress((void**)&pW18h, g_W18h);
    cudaGetSymbolAddress((void**)&pWch,  g_Wch);
    cudaGetSymbolAddress((void**)&pWdh,  g_Wdh);
    cudaGetSymbolAddress((void**)&pHph,  g_hph);

    const float* W18 = W1 + (size_t)8 * DIN * DHID;
    const float* b18 = b1 + 8 * DHID;
    const float* W12 = W1 + (size_t)2 * DIN * DHID;
    const float* b12 = b1 + 2 * DHID;
    const float* W28 = W2 + (size_t)8 * DHID * DOUT;
    const float* b28 = b2 + 8 * DOUT;

    constexpr int SM_WC   = 3 * (128 * 40 + 32 * 136) * 2;   // 56832 B
    constexpr int SM_MAIN = 3 * (128 * 40 + 32 * 264) * 2;   // 81408 B
    constexpr int SM_TAIL = 3 * (64 * 40 + 32 * 264) * 2;    // 66048 B

    auto kWc   = hgemm<2, 128, 256, 0>;   // 128x128, 8 warps, warp 64x32
    auto kMain = hgemm<2, 256, 512, 1>;   // 128x256, 16 warps, warp 64x32
    auto kTail = hgemm<1, 256, 256, 2>;   // 64x256,  8 warps, warp 64x32
    cudaFuncSetAttribute(kWc,   cudaFuncAttributeMaxDynamicSharedMemorySize, SM_WC);
    cudaFuncSetAttribute(kMain, cudaFuncAttributeMaxDynamicSharedMemorySize, SM_MAIN);
    cudaFuncSetAttribute(kTail, cudaFuncAttributeMaxDynamicSharedMemorySize, SM_TAIL);

    // 1. fp32 -> fp16 conversions (cpe into 16B-aligned padded layout)
    cvt_cpe_kernel<<<8192, 256>>>(cpe, pCpeh);
    cvt_kernel<<<(DPAIR * DIN / 2 + 255) / 256, 256>>>(Wi, pWih, DPAIR * DIN / 2);
    cvt_kernel<<<(DIN * DHID / 2 + 255) / 256, 256>>>(W18, pW18h, DIN * DHID / 2);

    // 2. Folded weights: Wc = Wi @ W18 (fp16), bc, g2, Wd, bd.
    kWc<<<dim3(DHID / 128, (DPAIR + 127) / 128), 256, SM_WC>>>(
        pWih, DIN, pW18h, pWch, DPAIR, DHID, DIN, nullptr, nullptr, nullptr);
    bc_kernel<<<2, 256>>>(bi, W18, b18);
    g2_kernel<<<Bb, DHID>>>(ac, W12, b12);
    wd_kernel<<<DHID / 16, 256>>>(W28, Wo1);
    bd_kernel<<<1, DOUT>>>(b28, Wo1, bo1);

    // 3. Main GEMM + h_p epilogue: [21568,1636] @ [1636,512] (fp16 MMA, 128x256).
    kMain<<<dim3(DHID / 256, (MROWS + 127) / 128), 512, SM_MAIN>>>(
        pCpeh, DPAIR_PAD, pWch, pHph, MROWS, DHID, DPAIR, nullptr, nullptr, nullptr);

    // 4. Fused tail: out = relu(h_p @ Wd + bd) . Wo2 + bo2  (hid never in gmem).
    kTail<<<dim3(1, MROWS / 64), 256, SM_TAIL>>>(
        pHph, DHID, pWdh, nullptr, MROWS, DOUT, DHID, Wo2, bo2, out);
}

// round 11
// speedup vs baseline: 1.1205x; 1.1205x over previous
#include <cuda_runtime.h>
#include <cuda_fp16.h>
#include <stdint.h>

#define Bb        32
#define NPAIR     674
#define DPAIR     1636
#define DPAIR_PAD 1640   // fp16 row stride: 3280 B, 16B-aligned for cp.async
#define DIN       768
#define DHID      512
#define DOUT      256
#define MROWS     21568  // Bb * NPAIR

// ---- scratch (static device globals) ----
__device__ __half g_cpeh[(size_t)MROWS * DPAIR_PAD];   // fp16 cpe, padded stride
__device__ __half g_Wih[DPAIR * DIN];                  // fp16 Wi
__device__ __half g_W18h[DIN * DHID];                  // fp16 W1[8]
__device__ __half g_Wch[DPAIR * DHID];                 // fp16 Wi @ W1[8]
__device__ __half g_Wdh[DHID * DOUT];                  // fp16 W2[8] @ Wo1
__device__ __half g_hph[(size_t)MROWS * DHID];         // fp16 h_p
__device__ float  g_bc[DHID];
__device__ float  g_g2[Bb * DHID];
__device__ float  g_bd[DOUT];

__device__ __forceinline__ void cp16(uint32_t saddr, const void* gptr, bool valid) {
    int sz = valid ? 16 : 0;   // src-size 0 -> zero-fill, no global read
    asm volatile("cp.async.cg.shared.global [%0], [%1], 16, %2;"
                 :: "r"(saddr), "l"(gptr), "r"(sz));
}
__device__ __forceinline__ void cp_commit() { asm volatile("cp.async.commit_group;"); }
template<int N>
__device__ __forceinline__ void cp_wait() {
    asm volatile("cp.async.wait_group %0;" :: "n"(N));
}

__device__ __forceinline__ void ldsm_x4(uint32_t* r, uint32_t addr) {
    asm volatile("ldmatrix.sync.aligned.m8n8.x4.shared.b16 {%0,%1,%2,%3}, [%4];"
                 : "=r"(r[0]), "=r"(r[1]), "=r"(r[2]), "=r"(r[3]) : "r"(addr));
}
__device__ __forceinline__ void ldsm_x4_t(uint32_t* r, uint32_t addr) {
    asm volatile("ldmatrix.sync.aligned.m8n8.x4.trans.shared.b16 {%0,%1,%2,%3}, [%4];"
                 : "=r"(r[0]), "=r"(r[1]), "=r"(r[2]), "=r"(r[3]) : "r"(addr));
}
__device__ __forceinline__ void mma_f16(float* d, const uint32_t* a, const uint32_t* b) {
    asm volatile(
        "mma.sync.aligned.m16n8k16.row.col.f32.f16.f16.f32 "
        "{%0,%1,%2,%3}, {%4,%5,%6,%7}, {%8,%9}, {%0,%1,%2,%3};"
        : "+f"(d[0]), "+f"(d[1]), "+f"(d[2]), "+f"(d[3])
        : "r"(a[0]), "r"(a[1]), "r"(a[2]), "r"(a[3]), "r"(b[0]), "r"(b[1]));
}

// ============================================================================
// Pipelined FP16 MMA GEMM (fp32 accumulate). Block tile (NWM*64) x BN, BK=32,
// NS-stage cp.async (wait_group NS-2, single __syncthreads per iteration),
// ldmatrix fragments, warp tile 64 x WTN via m16n8k16.
// Safety of the single barrier: the load at iter `it` targets stage
// (it+NS-1)%NS == (it-1)%NS, which was last READ in iter it-1; every warp has
// passed this iteration's barrier, hence finished those reads. wait_group NS-2
// guarantees the group for stage it%NS has landed.
// A row-major [M,K] fp16 with row stride lda (lda*2 16B-aligned),
// B row-major [K,N] fp16 (N % BN == 0). OOB rows/k zero-filled.
// EPI=0: C = half(A@B)
// EPI=1: C = half(relu((A@B + g_bc[n] + g_g2[row/674][n]) * 0.5))
// EPI=2: out[row] = dot(relu(A@B + g_bd), Wo2) + bo2   (C unused)
// ============================================================================
template<int NWM, int BN, int NTHREADS, int EPI, int NS>
__global__ __launch_bounds__(NTHREADS) void hgemm(
    const __half* __restrict__ A, int lda, const __half* __restrict__ Bm,
    __half* __restrict__ C, int M, int N, int K,
    const float* __restrict__ Wo2, const float* __restrict__ bo2,
    float* __restrict__ out)
{
    constexpr int BM   = NWM * 64;
    constexpr int NWN  = NTHREADS / 32 / NWM;
    constexpr int WTN  = BN / NWN;     // warp tile n
    constexpr int NTN  = WTN / 8;      // n8 sub-tiles per warp
    constexpr int NPB  = WTN / 16;     // B ldmatrix.x4 per k16
    constexpr int SA   = 40;           // halves per A smem row (80 B)
    constexpr int SB   = BN + 8;       // halves per B smem row
    constexpr int ASTG = BM * SA;
    constexpr int BSTG = 32 * SB;

    extern __shared__ char smraw[];
    const uint32_t smb  = (uint32_t)__cvta_generic_to_shared(smraw);
    const uint32_t bsmb = smb + NS * ASTG * 2;

    const int tid  = threadIdx.x;
    const int lane = tid & 31;
    const int wid  = tid >> 5;
    const int wm   = wid / NWN;
    const int wn   = wid % NWN;
    const int m0   = blockIdx.y * BM;
    const int n0   = blockIdx.x * BN;
    const int q    = lane & 3;
    const int g    = lane >> 2;

    float acc[4][NTN][4];
    #pragma unroll
    for (int mt = 0; mt < 4; mt++)
        #pragma unroll
        for (int nt = 0; nt < NTN; nt++)
            #pragma unroll
            for (int i = 0; i < 4; i++) acc[mt][nt][i] = 0.f;

    const int niter = (K + 31) >> 5;

    auto load_stage = [&](int s, int k0) {
        const uint32_t abase = smb + (uint32_t)(s * ASTG) * 2;
        for (int qx = tid; qx < BM * 4; qx += NTHREADS) {
            const int row  = qx >> 2;
            const int kseg = (qx & 3) * 8;
            const bool v = (m0 + row < M) && (k0 + kseg < K);
            cp16(abase + (uint32_t)(row * SA + kseg) * 2,
                 A + (size_t)(m0 + row) * lda + k0 + kseg, v);
        }
        const uint32_t bbase = bsmb + (uint32_t)(s * BSTG) * 2;
        for (int qx = tid; qx < 32 * (BN / 8); qx += NTHREADS) {
            const int row  = qx / (BN / 8);
            const int nseg = (qx % (BN / 8)) * 8;
            const bool v = (k0 + row) < K;
            cp16(bbase + (uint32_t)(row * SB + nseg) * 2,
                 Bm + (size_t)(k0 + row) * N + n0 + nseg, v);
        }
    };

    #pragma unroll
    for (int s = 0; s < NS - 1; s++) {
        load_stage(s, s * 32);
        cp_commit();
    }

    const uint32_t a_ld0 = smb +
        (uint32_t)((wm * 64 + (lane & 15)) * SA + (lane >> 4) * 8) * 2;
    const uint32_t b_ld0 = bsmb +
        (uint32_t)(((lane & 7) + ((lane >> 3) & 1) * 8) * SB
                   + wn * WTN + (lane >> 4) * 8) * 2;

    for (int it = 0; it < niter; it++) {
        cp_wait<NS - 2>();
        __syncthreads();

        const int nxt = it + NS - 1;
        if (nxt < niter) load_stage(nxt % NS, nxt * 32);
        cp_commit();

        const uint32_t ast = (uint32_t)((it % NS) * ASTG) * 2;
        const uint32_t bst = (uint32_t)((it % NS) * BSTG) * 2;

        #pragma unroll
        for (int k16 = 0; k16 < 2; k16++) {
            uint32_t af[4][4], bf[NPB][4];
            const uint32_t aaddr = a_ld0 + ast + (uint32_t)(k16 * 16) * 2;
            #pragma unroll
            for (int mt = 0; mt < 4; mt++)
                ldsm_x4(af[mt], aaddr + (uint32_t)(mt * 16 * SA) * 2);
            const uint32_t baddr = b_ld0 + bst + (uint32_t)(k16 * 16 * SB) * 2;
            #pragma unroll
            for (int np = 0; np < NPB; np++)
                ldsm_x4_t(bf[np], baddr + (uint32_t)(np * 16) * 2);
            #pragma unroll
            for (int mt = 0; mt < 4; mt++)
                #pragma unroll
                for (int nt = 0; nt < NTN; nt++)
                    mma_f16(acc[mt][nt], af[mt], &bf[nt >> 1][(nt & 1) * 2]);
        }
    }

    if (EPI == 0 || EPI == 1) {
        #pragma unroll
        for (int mt = 0; mt < 4; mt++) {
            #pragma unroll
            for (int half = 0; half < 2; half++) {
                const int r = m0 + wm * 64 + mt * 16 + g + half * 8;
                if (r >= M) continue;
                const float* g2r = (EPI == 1) ? (g_g2 + (r / NPAIR) * DHID) : nullptr;
                #pragma unroll
                for (int nt = 0; nt < NTN; nt++) {
                    const int c = n0 + wn * WTN + nt * 8 + 2 * q;
                    float v0 = acc[mt][nt][half * 2 + 0];
                    float v1 = acc[mt][nt][half * 2 + 1];
                    if (EPI == 1) {
                        v0 = fmaxf((v0 + g_bc[c    ] + g2r[c    ]) * 0.5f, 0.f);
                        v1 = fmaxf((v1 + g_bc[c + 1] + g2r[c + 1]) * 0.5f, 0.f);
                    }
                    *(__half2*)(C + (size_t)r * N + c) = __floats2half2_rn(v0, v1);
                }
            }
        }
    } else {
        // EPI == 2: fused out[r] = dot(relu(acc + g_bd), Wo2) + bo2
        float bdv[NTN][2], wv[NTN][2];
        #pragma unroll
        for (int nt = 0; nt < NTN; nt++)
            #pragma unroll
            for (int j = 0; j < 2; j++) {
                const int c = wn * WTN + nt * 8 + 2 * q + j;
                bdv[nt][j] = g_bd[c];
                wv[nt][j]  = Wo2[c];
            }
        cp_wait<0>();
        __syncthreads();              // drain before smem reuse
        float* red = (float*)smraw;   // [BM][NWN]
        #pragma unroll
        for (int mt = 0; mt < 4; mt++) {
            #pragma unroll
            for (int half = 0; half < 2; half++) {
                float p = 0.f;
                #pragma unroll
                for (int nt = 0; nt < NTN; nt++)
                    #pragma unroll
                    for (int j = 0; j < 2; j++) {
                        const float h = fmaxf(acc[mt][nt][half * 2 + j] + bdv[nt][j], 0.f);
                        p = fmaf(h, wv[nt][j], p);
                    }
                p += __shfl_xor_sync(0xffffffffu, p, 1);
                p += __shfl_xor_sync(0xffffffffu, p, 2);
                if (q == 0) {
                    const int rl = wm * 64 + mt * 16 + g + half * 8;
                    red[rl * NWN + wn] = p;
                }
            }
        }
        __syncthreads();
        if (tid < BM) {
            float s = bo2[0];
            #pragma unroll
            for (int w = 0; w < NWN; w++) s += red[tid * NWN + w];
            if (m0 + tid < M) out[m0 + tid] = s;
        }
    }
}

// ---- fp32 -> fp16 bulk convert, contiguous ----
__global__ void cvt_kernel(const float* __restrict__ in, __half* __restrict__ out, int n2)
{
    const float2* i2 = (const float2*)in;
    __half2* o2 = (__half2*)out;
    for (int i = blockIdx.x * blockDim.x + threadIdx.x; i < n2;
         i += gridDim.x * blockDim.x)
        o2[i] = __float22half2_rn(i2[i]);
}

// ---- cpe fp32 [MROWS x DPAIR] -> fp16 padded [MROWS x DPAIR_PAD], pad zeroed ----
__global__ void cvt_cpe_kernel(const float* __restrict__ in, __half* __restrict__ out)
{
    const int nseg = DPAIR / 4;   // 409 float4 segs per row
    for (int idx = blockIdx.x * blockDim.x + threadIdx.x; idx < MROWS * nseg;
         idx += gridDim.x * blockDim.x) {
        const int row = idx / nseg;
        const int c4  = (idx % nseg) * 4;
        float4 v = *(const float4*)(in + (size_t)row * DPAIR + c4);
        __half2* dst = (__half2*)(out + (size_t)row * DPAIR_PAD + c4);
        dst[0] = __floats2half2_rn(v.x, v.y);
        dst[1] = __floats2half2_rn(v.z, v.w);
        if (c4 == 0) {
            __half2* pad = (__half2*)(out + (size_t)row * DPAIR_PAD + DPAIR);
            pad[0] = __half2half2(__float2half(0.f));
            pad[1] = __half2half2(__float2half(0.f));
        }
    }
}

// ---- small precompute kernels ----
__global__ void bc_kernel(const float* __restrict__ bi, const float* __restrict__ W18,
                          const float* __restrict__ b18)
{
    const int n = blockIdx.x * blockDim.x + threadIdx.x;
    float s = 0.f;
    for (int k = 0; k < DIN; k++) s = fmaf(bi[k], W18[(size_t)k * DHID + n], s);
    g_bc[n] = s + b18[n];
}

__global__ void g2_kernel(const float* __restrict__ ac, const float* __restrict__ W12,
                          const float* __restrict__ b12)
{
    const int b = blockIdx.x;
    const int n = threadIdx.x;
    const float scale = rsqrtf((float)NPAIR);
    float s = 0.f;
    const float* arow = ac + (size_t)b * DIN;
    for (int k = 0; k < DIN; k++) s = fmaf(arow[k], W12[(size_t)k * DHID + n], s);
    g_g2[b * DHID + n] = s * scale + b12[n];
}

// Wd = W2[8] @ Wo1 -> fp16. 16 m-rows per block via smem tile, Wo1 coalesced.
__global__ __launch_bounds__(256) void wd_kernel(const float* __restrict__ W28,
                                                 const float* __restrict__ Wo1)
{
    __shared__ float w28s[16][DOUT];
    const int m0 = blockIdx.x * 16;
    const int n  = threadIdx.x;
    for (int i = threadIdx.x; i < 16 * DOUT; i += 256)
        w28s[i >> 8][i & 255] = W28[(size_t)(m0 + (i >> 8)) * DOUT + (i & 255)];
    __syncthreads();
    float acc[16];
    #pragma unroll
    for (int mm = 0; mm < 16; mm++) acc[mm] = 0.f;
    for (int k = 0; k < DOUT; k++) {
        const float w = Wo1[(size_t)k * DOUT + n];
        #pragma unroll
        for (int mm = 0; mm < 16; mm++) acc[mm] = fmaf(w28s[mm][k], w, acc[mm]);
    }
    #pragma unroll
    for (int mm = 0; mm < 16; mm++)
        g_Wdh[(size_t)(m0 + mm) * DOUT + n] = __float2half_rn(acc[mm]);
}

__global__ void bd_kernel(const float* __restrict__ b28, const float* __restrict__ Wo1,
                          const float* __restrict__ bo1)
{
    const int n = threadIdx.x;
    float s = 0.f;
    for (int k = 0; k < DOUT; k++) s = fmaf(b28[k], Wo1[(size_t)k * DOUT + n], s);
    g_bd[n] = s + bo1[n];
}

// ============================================================================
// Launch. Live inputs: cpe(0), ac(3), Wi(4), bi(5), W1(6), b1(7), W2(8),
// b2(9), Wo1(10), bo1(11), Wo2(12), bo2(13). he/hc dead.
// ============================================================================
extern "C" void kernel_launch(void* const* d_in, const int* in_sizes, int n_in,
                              void* d_out, int out_size)
{
    const float* cpe = (const float*)d_in[0];
    const float* ac  = (const float*)d_in[3];
    const float* Wi  = (const float*)d_in[4];
    const float* bi  = (const float*)d_in[5];
    const float* W1  = (const float*)d_in[6];
    const float* b1  = (const float*)d_in[7];
    const float* W2  = (const float*)d_in[8];
    const float* b2  = (const float*)d_in[9];
    const float* Wo1 = (const float*)d_in[10];
    const float* bo1 = (const float*)d_in[11];
    const float* Wo2 = (const float*)d_in[12];
    const float* bo2 = (const float*)d_in[13];
    float* out = (float*)d_out;

    __half *pCpeh, *pWih, *pW18h, *pWch, *pWdh, *pHph;
    cudaGetSymbolAddress((void**)&pCpeh, g_cpeh);
    cudaGetSymbolAddress((void**)&pWih,  g_Wih);
    cudaGetSymbolAddress((void**)&pW18h, g_W18h);
    cudaGetSymbolAddress((void**)&pWch,  g_Wch);
    cudaGetSymbolAddress((void**)&pWdh,  g_Wdh);
    cudaGetSymbolAddress((void**)&pHph,  g_hph);

    const float* W18 = W1 + (size_t)8 * DIN * DHID;
    const float* b18 = b1 + 8 * DHID;
    const float* W12 = W1 + (size_t)2 * DIN * DHID;
    const float* b12 = b1 + 2 * DHID;
    const float* W28 = W2 + (size_t)8 * DHID * DOUT;
    const float* b28 = b2 + 8 * DOUT;

    constexpr int SM_MAIN = 4 * (128 * 40 + 32 * 136) * 2;   // 75776 B
    constexpr int SM_TAIL = 4 * (64 * 40 + 32 * 264) * 2;    // 88064 B

    auto kWc   = hgemm<2, 128, 256, 0, 4>;   // 128x128, 8 warps, warp 64x32
    auto kMain = hgemm<2, 128, 256, 1, 4>;   // 128x128, 8 warps, warp 64x32
    auto kTail = hgemm<1, 256, 256, 2, 4>;   // 64x256,  8 warps, warp 64x32
    cudaFuncSetAttribute(kWc,   cudaFuncAttributeMaxDynamicSharedMemorySize, SM_MAIN);
    cudaFuncSetAttribute(kMain, cudaFuncAttributeMaxDynamicSharedMemorySize, SM_MAIN);
    cudaFuncSetAttribute(kTail, cudaFuncAttributeMaxDynamicSharedMemorySize, SM_TAIL);

    // 1. fp32 -> fp16 conversions (cpe into 16B-aligned padded layout)
    cvt_cpe_kernel<<<8192, 256>>>(cpe, pCpeh);
    cvt_kernel<<<(DPAIR * DIN / 2 + 255) / 256, 256>>>(Wi, pWih, DPAIR * DIN / 2);
    cvt_kernel<<<(DIN * DHID / 2 + 255) / 256, 256>>>(W18, pW18h, DIN * DHID / 2);

    // 2. Folded weights: Wc = Wi @ W18 (fp16), bc, g2, Wd, bd.
    kWc<<<dim3(DHID / 128, (DPAIR + 127) / 128), 256, SM_MAIN>>>(
        pWih, DIN, pW18h, pWch, DPAIR, DHID, DIN, nullptr, nullptr, nullptr);
    bc_kernel<<<2, 256>>>(bi, W18, b18);
    g2_kernel<<<Bb, DHID>>>(ac, W12, b12);
    wd_kernel<<<DHID / 16, 256>>>(W28, Wo1);
    bd_kernel<<<1, DOUT>>>(b28, Wo1, bo1);

    // 3. Main GEMM + h_p epilogue: [21568,1636] @ [1636,512] (fp16 MMA, 128x128).
    kMain<<<dim3(DHID / 128, (MROWS + 127) / 128), 256, SM_MAIN>>>(
        pCpeh, DPAIR_PAD, pWch, pHph, MROWS, DHID, DPAIR, nullptr, nullptr, nullptr);

    // 4. Fused tail: out = relu(h_p @ Wd + bd) . Wo2 + bo2  (hid never in gmem).
    kTail<<<dim3(1, MROWS / 64), 256, SM_TAIL>>>(
        pHph, DHID, pWdh, nullptr, MROWS, DOUT, DHID, Wo2, bo2, out);
}